// round 13
// baseline (speedup 1.0000x reference)
#include <cuda_runtime.h>
#include <cuda_fp16.h>
#include <cstdint>

// Problem constants
#define Bb   8
#define Lseq 8192
#define Hd   768
#define Mtot (Bb * Lseq)        // 65536
#define LAMK 0.1f

// GEMM tiling (fp16 mma.sync path, fp16 accumulate)
#define KT    24                // K chunks of 32
#define RSB   80                // smem row stride bytes (40 halves) -> conflict-free ldmatrix
#define ATILE 10240             // 128 rows * 80B
#define STG   20480             // A tile + B tile per stage
#define NSTG  3
#define GSM   (NSTG * STG)      // 61440 bytes dynamic smem -> 3 CTAs/SM

// ---------------- scratch ----------------------------------------------------
__device__ __half g_vh[(size_t)Mtot * Hd];      // silu(x*D + conv) in fp16
__device__ __half g_wh[2 * Hd * Hd];            // W in fp16 (1536 x 768)
__device__ int    g_tap_idx[Hd * Lseq];
__device__ float  g_tap_val[Hd * Lseq];
__device__ int    g_tap_cnt[Hd];

// ---------------- helpers ----------------------------------------------------
__device__ __forceinline__ float sigmoidf_(float z) {
    return 1.0f / (1.0f + __expf(-z));
}

__device__ __forceinline__ uint32_t s2u(const void* p) {
    uint32_t a;
    asm("{ .reg .u64 t; cvta.to.shared.u64 t, %1; cvt.u32.u64 %0, t; }"
        : "=r"(a) : "l"(p));
    return a;
}

__device__ __forceinline__ void cp16(uint32_t dst, const void* src) {
    asm volatile("cp.async.cg.shared.global [%0], [%1], 16;\n"
                 :: "r"(dst), "l"(src));
}

__device__ __forceinline__ void ldsm4(uint32_t* r, uint32_t addr) {
    asm volatile("ldmatrix.sync.aligned.m8n8.x4.shared.b16 {%0,%1,%2,%3}, [%4];"
                 : "=r"(r[0]), "=r"(r[1]), "=r"(r[2]), "=r"(r[3]) : "r"(addr));
}

// fp16-accumulate mma: D,C are 2 regs of f16x2
__device__ __forceinline__ void mma16816h(uint32_t* d, const uint32_t* a,
                                          uint32_t b0, uint32_t b1) {
    asm volatile(
        "mma.sync.aligned.m16n8k16.row.col.f16.f16.f16.f16 "
        "{%0,%1}, {%2,%3,%4,%5}, {%6,%7}, {%0,%1};\n"
        : "+r"(d[0]), "+r"(d[1])
        : "r"(a[0]), "r"(a[1]), "r"(a[2]), "r"(a[3]), "r"(b0), "r"(b1));
}

// ---------------- kernel 0: W fp32 -> fp16 -----------------------------------
__global__ void wconv_kernel(const float* __restrict__ W) {
    int i = blockIdx.x * 256 + threadIdx.x;
    g_wh[i] = __float2half_rn(W[i]);
}

// ---------------- kernel 1: soft-threshold + ordered tap compaction ----------
__global__ void build_taps_kernel(const float* __restrict__ kern) {
    int h = blockIdx.x * 8 + (threadIdx.x >> 5);
    int lane = threadIdx.x & 31;
    const float* kr = kern + (size_t)h * Lseq;
    int* ti = g_tap_idx + (size_t)h * Lseq;
    float* tv = g_tap_val + (size_t)h * Lseq;
    int cnt = 0;
    for (int base = 0; base < Lseq; base += 32) {
        float kv = kr[base + lane];
        float mag = fabsf(kv) - LAMK;
        bool p = mag > 0.0f;
        unsigned msk = __ballot_sync(0xffffffffu, p);
        if (p) {
            int pos = cnt + __popc(msk & ((1u << lane) - 1u));
            ti[pos] = base + lane;
            tv[pos] = copysignf(mag, kv);
        }
        cnt += __popc(msk);
    }
    if (lane == 0) g_tap_cnt[h] = cnt;
}

// ---------------- kernel 2: v = silu(x*D + sparse_causal_conv) -> fp16 -------
__global__ void prep_v_kernel(const float* __restrict__ x, const float* __restrict__ D) {
    const int H4 = Hd / 4;
    int i = blockIdx.x * blockDim.x + threadIdx.x;
    int m = i / H4;
    int h4 = (i - m * H4) * 4;

    float4 xv = *reinterpret_cast<const float4*>(x + (size_t)m * Hd + h4);
    float4 dv = *reinterpret_cast<const float4*>(D + h4);
    float s[4] = { xv.x * dv.x, xv.y * dv.y, xv.z * dv.z, xv.w * dv.w };

#pragma unroll
    for (int c = 0; c < 4; ++c) {
        int h = h4 + c;
        int cnt = g_tap_cnt[h];
        if (cnt > 0) {                         // cold path (taps survive threshold)
            int l = m & (Lseq - 1);
            int b = m >> 13;
            const int* ti = g_tap_idx + (size_t)h * Lseq;
            const float* tv = g_tap_val + (size_t)h * Lseq;
            float acc = 0.0f;
            for (int t = 0; t < cnt; ++t) {
                int j = ti[t];
                if (j <= l)
                    acc += tv[t] * x[((size_t)b * Lseq + (l - j)) * Hd + h];
            }
            s[c] += acc;
        }
    }

    __half2 h01 = __floats2half2_rn(s[0] * sigmoidf_(s[0]), s[1] * sigmoidf_(s[1]));
    __half2 h23 = __floats2half2_rn(s[2] * sigmoidf_(s[2]), s[3] * sigmoidf_(s[3]));
    uint2 pk;
    pk.x = *reinterpret_cast<uint32_t*>(&h01);
    pk.y = *reinterpret_cast<uint32_t*>(&h23);
    *reinterpret_cast<uint2*>(g_vh + (size_t)m * Hd + h4) = pk;
}

// ---------------- kernel 3: fp16 mma GEMM (f16 acc) + bias + GLU + residual --
// CTA: 128 M-rows x (64 a-cols + matching 64 g-cols). B smem rows 0..63 = W row
// n0+r, rows 64..127 = W row 768+n0+r. GLU fused in epilogue. 3 CTAs/SM.
// ks substeps staggered by warp parity to de-phase LDS bursts vs MMA phases.
__global__ void __launch_bounds__(256, 3)
gemm_fp16_kernel(const float* __restrict__ bias, const float* __restrict__ x,
                 float* __restrict__ out) {
    extern __shared__ char dsm[];
    uint32_t sb = s2u(dsm);
    const int tid  = threadIdx.x;
    const int lane = tid & 31;
    const int warp = tid >> 5;
    const int wm = warp >> 2;            // 0..1 -> 64 M-rows each
    const int wn = warp & 3;             // 0..3 -> 16 a-cols (+16 g-cols) each
    const int m0 = blockIdx.y * 128;
    const int n0 = blockIdx.x * 64;
    const int wpar = warp & 1;           // ks stagger parity

    // global->smem loader mapping: each thread owns 2 A units + 2 B units/stage
    const int i0 = tid, i1 = tid + 256;
    const int ar0 = i0 >> 2, au0 = i0 & 3;
    const int ar1 = i1 >> 2, au1 = i1 & 3;
    const __half* asrc0 = g_vh + (size_t)(m0 + ar0) * Hd + au0 * 8;
    const __half* asrc1 = g_vh + (size_t)(m0 + ar1) * Hd + au1 * 8;
    const int wr0 = (ar0 < 64) ? (n0 + ar0) : (704 + n0 + ar0);
    const int wr1 = (ar1 < 64) ? (n0 + ar1) : (704 + n0 + ar1);
    const __half* bsrc0 = g_wh + (size_t)wr0 * Hd + au0 * 8;
    const __half* bsrc1 = g_wh + (size_t)wr1 * Hd + au1 * 8;
    const uint32_t ad0 = (uint32_t)(ar0 * RSB + au0 * 16);
    const uint32_t ad1 = (uint32_t)(ar1 * RSB + au1 * 16);

    // prologue: stages 0..1
#pragma unroll
    for (int s = 0; s < 2; ++s) {
        uint32_t st = sb + s * STG;
        cp16(st + ad0, asrc0 + s * 32);
        cp16(st + ad1, asrc1 + s * 32);
        cp16(st + ATILE + ad0, bsrc0 + s * 32);
        cp16(st + ATILE + ad1, bsrc1 + s * 32);
        asm volatile("cp.async.commit_group;" ::: "memory");
    }

    // ldmatrix per-lane offsets
    const int lro = (lane & 7) + ((lane >> 3) & 1) * 8;
    const int lu  = lane >> 4;
    uint32_t aoff[4], boff[2];
#pragma unroll
    for (int mi = 0; mi < 4; ++mi)
        aoff[mi] = (uint32_t)((wm * 64 + mi * 16 + lro) * RSB + lu * 16);
    boff[0] = (uint32_t)((wn * 16 + lro) * RSB + lu * 16);
    boff[1] = (uint32_t)((64 + wn * 16 + lro) * RSB + lu * 16);

    uint32_t accA[4][2][2], accG[4][2][2];    // f16x2 accumulators
#pragma unroll
    for (int mi = 0; mi < 4; ++mi)
#pragma unroll
        for (int nj = 0; nj < 2; ++nj)
#pragma unroll
            for (int r = 0; r < 2; ++r) { accA[mi][nj][r] = 0u; accG[mi][nj][r] = 0u; }

    for (int t = 0; t < KT; ++t) {
        asm volatile("cp.async.wait_group 1;" ::: "memory");
        __syncthreads();

        if (t + 2 < KT) {
            uint32_t st = sb + ((t + 2) % NSTG) * STG;
            int kw = (t + 2) * 32;
            cp16(st + ad0, asrc0 + kw);
            cp16(st + ad1, asrc1 + kw);
            cp16(st + ATILE + ad0, bsrc0 + kw);
            cp16(st + ATILE + ad1, bsrc1 + kw);
        }
        asm volatile("cp.async.commit_group;" ::: "memory");

        uint32_t ab = sb + (t % NSTG) * STG;
        uint32_t bb = ab + ATILE;
#pragma unroll
        for (int ks = 0; ks < 2; ++ks) {
            // warp-parity stagger: even warps do ks 0,1; odd warps do 1,0
            uint32_t kadd = (uint32_t)((ks ^ wpar) * 32);   // 16 halves = 32B
            uint32_t afr[4][4];
#pragma unroll
            for (int mi = 0; mi < 4; ++mi)
                ldsm4(afr[mi], ab + aoff[mi] + kadd);
            uint32_t ba[4], bg[4];
            ldsm4(ba, bb + boff[0] + kadd);
            ldsm4(bg, bb + boff[1] + kadd);
#pragma unroll
            for (int mi = 0; mi < 4; ++mi) {
                mma16816h(accA[mi][0], afr[mi], ba[0], ba[2]);
                mma16816h(accA[mi][1], afr[mi], ba[1], ba[3]);
                mma16816h(accG[mi][0], afr[mi], bg[0], bg[2]);
                mma16816h(accG[mi][1], afr[mi], bg[1], bg[3]);
            }
        }
    }

    // epilogue: unpack f16 accs, bias + GLU + residual
    const int r  = lane >> 2;
    const int c2 = (lane & 3) * 2;
#pragma unroll
    for (int nj = 0; nj < 2; ++nj) {
        int col = n0 + wn * 16 + nj * 8 + c2;
        float ba0 = __ldg(bias + col),      ba1 = __ldg(bias + col + 1);
        float bg0 = __ldg(bias + Hd + col), bg1 = __ldg(bias + Hd + col + 1);
#pragma unroll
        for (int mi = 0; mi < 4; ++mi) {
            int mrow = m0 + wm * 64 + mi * 16 + r;
            {
                __half2 ah = *reinterpret_cast<__half2*>(&accA[mi][nj][0]);
                __half2 gh = *reinterpret_cast<__half2*>(&accG[mi][nj][0]);
                float a0 = __low2float(ah) + ba0, a1 = __high2float(ah) + ba1;
                float g0 = __low2float(gh) + bg0, g1 = __high2float(gh) + bg1;
                float2 xv = __ldg(reinterpret_cast<const float2*>(x + (size_t)mrow * Hd + col));
                float2 o;
                o.x = a0 * sigmoidf_(g0) + xv.x;
                o.y = a1 * sigmoidf_(g1) + xv.y;
                *reinterpret_cast<float2*>(out + (size_t)mrow * Hd + col) = o;
            }
            {
                int mr2 = mrow + 8;
                __half2 ah = *reinterpret_cast<__half2*>(&accA[mi][nj][1]);
                __half2 gh = *reinterpret_cast<__half2*>(&accG[mi][nj][1]);
                float a0 = __low2float(ah) + ba0, a1 = __high2float(ah) + ba1;
                float g0 = __low2float(gh) + bg0, g1 = __high2float(gh) + bg1;
                float2 xv = __ldg(reinterpret_cast<const float2*>(x + (size_t)mr2 * Hd + col));
                float2 o;
                o.x = a0 * sigmoidf_(g0) + xv.x;
                o.y = a1 * sigmoidf_(g1) + xv.y;
                *reinterpret_cast<float2*>(out + (size_t)mr2 * Hd + col) = o;
            }
        }
    }
}

// ---------------- launch ------------------------------------------------------
extern "C" void kernel_launch(void* const* d_in, const int* in_sizes, int n_in,
                              void* d_out, int out_size) {
    const float* x    = (const float*)d_in[0];   // (8, 8192, 768)
    const float* kern = (const float*)d_in[1];   // (1, 768, 8192)
    const float* D    = (const float*)d_in[2];   // (1, 768)
    const float* W    = (const float*)d_in[3];   // (1536, 768)
    const float* bias = (const float*)d_in[4];   // (1536,)
    float* out = (float*)d_out;                  // (8, 8192, 768)

    cudaFuncSetAttribute(gemm_fp16_kernel,
                         cudaFuncAttributeMaxDynamicSharedMemorySize, GSM);

    wconv_kernel<<<(2 * Hd * Hd) / 256, 256>>>(W);
    build_taps_kernel<<<Hd / 8, 256>>>(kern);

    int tot4 = Mtot * (Hd / 4);
    prep_v_kernel<<<tot4 / 256, 256>>>(x, D);

    dim3 grid(Hd / 64, Mtot / 128);              // (12, 512)
    gemm_fp16_kernel<<<grid, 256, GSM>>>(bias, x, out);
}

// round 14
// speedup vs baseline: 1.0213x; 1.0213x over previous
#include <cuda_runtime.h>
#include <cuda_fp16.h>
#include <cstdint>

// Problem constants
#define Bb   8
#define Lseq 8192
#define Hd   768
#define Mtot (Bb * Lseq)        // 65536
#define LAMK 0.1f

// GEMM tiling (fp16 mma.sync path, fp16 accumulate)
#define KT    24                // K chunks of 32
#define RSB   80                // smem row stride bytes (40 halves) -> conflict-free ldmatrix
#define ATILE 10240             // 128 rows * 80B
#define STG   20480             // A tile + B tile per stage
#define NSTG  3
#define GSM   (NSTG * STG)      // 61440 bytes dynamic smem -> 3 CTAs/SM

// ---------------- scratch ----------------------------------------------------
__device__ __half g_vh[(size_t)Mtot * Hd];      // silu(x*D + conv) in fp16
__device__ __half g_wh[2 * Hd * Hd];            // W in fp16 (1536 x 768)
__device__ int    g_tap_idx[Hd * Lseq];
__device__ float  g_tap_val[Hd * Lseq];
__device__ int    g_tap_cnt[Hd];

// ---------------- helpers ----------------------------------------------------
__device__ __forceinline__ float sigmoidf_(float z) {
    return 1.0f / (1.0f + __expf(-z));
}

__device__ __forceinline__ uint32_t s2u(const void* p) {
    uint32_t a;
    asm("{ .reg .u64 t; cvta.to.shared.u64 t, %1; cvt.u32.u64 %0, t; }"
        : "=r"(a) : "l"(p));
    return a;
}

__device__ __forceinline__ void cp16(uint32_t dst, const void* src) {
    asm volatile("cp.async.cg.shared.global [%0], [%1], 16;\n"
                 :: "r"(dst), "l"(src));
}

__device__ __forceinline__ void ldsm4(uint32_t* r, uint32_t addr) {
    asm volatile("ldmatrix.sync.aligned.m8n8.x4.shared.b16 {%0,%1,%2,%3}, [%4];"
                 : "=r"(r[0]), "=r"(r[1]), "=r"(r[2]), "=r"(r[3]) : "r"(addr));
}

// fp16-accumulate mma: D,C are 2 regs of f16x2
__device__ __forceinline__ void mma16816h(uint32_t* d, const uint32_t* a,
                                          uint32_t b0, uint32_t b1) {
    asm volatile(
        "mma.sync.aligned.m16n8k16.row.col.f16.f16.f16.f16 "
        "{%0,%1}, {%2,%3,%4,%5}, {%6,%7}, {%0,%1};\n"
        : "+r"(d[0]), "+r"(d[1])
        : "r"(a[0]), "r"(a[1]), "r"(a[2]), "r"(a[3]), "r"(b0), "r"(b1));
}

// ---------------- kernel 1: fused W fp32->fp16 + tap compaction --------------
// blocks [0,96): soft-threshold + ordered tap compaction (8 warps = 8 h each)
// blocks [96,4704): W conversion (256 elements each)
__global__ void init_kernel(const float* __restrict__ kern,
                            const float* __restrict__ W) {
    if (blockIdx.x >= 96) {
        int i = (blockIdx.x - 96) * 256 + threadIdx.x;
        g_wh[i] = __float2half_rn(W[i]);
        return;
    }
    int h = blockIdx.x * 8 + (threadIdx.x >> 5);
    int lane = threadIdx.x & 31;
    const float* kr = kern + (size_t)h * Lseq;
    int* ti = g_tap_idx + (size_t)h * Lseq;
    float* tv = g_tap_val + (size_t)h * Lseq;
    int cnt = 0;
    for (int base = 0; base < Lseq; base += 32) {
        float kv = kr[base + lane];
        float mag = fabsf(kv) - LAMK;
        bool p = mag > 0.0f;
        unsigned msk = __ballot_sync(0xffffffffu, p);
        if (p) {
            int pos = cnt + __popc(msk & ((1u << lane) - 1u));
            ti[pos] = base + lane;
            tv[pos] = copysignf(mag, kv);
        }
        cnt += __popc(msk);
    }
    if (lane == 0) g_tap_cnt[h] = cnt;
}

// ---------------- kernel 2: v = silu(x*D + sparse_causal_conv) -> fp16 -------
// Each thread processes 2 float4 units (MLP=2), units j and j + tot4/2.
__device__ __forceinline__ void prep_unit(int i, const float* __restrict__ x,
                                          const float* __restrict__ D) {
    const int H4 = Hd / 4;
    int m = i / H4;
    int h4 = (i - m * H4) * 4;

    float4 xv = *reinterpret_cast<const float4*>(x + (size_t)m * Hd + h4);
    float4 dv = *reinterpret_cast<const float4*>(D + h4);
    float s[4] = { xv.x * dv.x, xv.y * dv.y, xv.z * dv.z, xv.w * dv.w };

#pragma unroll
    for (int c = 0; c < 4; ++c) {
        int h = h4 + c;
        int cnt = g_tap_cnt[h];
        if (cnt > 0) {                         // cold path (taps survive threshold)
            int l = m & (Lseq - 1);
            int b = m >> 13;
            const int* ti = g_tap_idx + (size_t)h * Lseq;
            const float* tv = g_tap_val + (size_t)h * Lseq;
            float acc = 0.0f;
            for (int t = 0; t < cnt; ++t) {
                int j = ti[t];
                if (j <= l)
                    acc += tv[t] * x[((size_t)b * Lseq + (l - j)) * Hd + h];
            }
            s[c] += acc;
        }
    }

    __half2 h01 = __floats2half2_rn(s[0] * sigmoidf_(s[0]), s[1] * sigmoidf_(s[1]));
    __half2 h23 = __floats2half2_rn(s[2] * sigmoidf_(s[2]), s[3] * sigmoidf_(s[3]));
    uint2 pk;
    pk.x = *reinterpret_cast<uint32_t*>(&h01);
    pk.y = *reinterpret_cast<uint32_t*>(&h23);
    *reinterpret_cast<uint2*>(g_vh + (size_t)m * Hd + h4) = pk;
}

__global__ void prep_v_kernel(const float* __restrict__ x, const float* __restrict__ D) {
    const int half = Mtot * (Hd / 4) / 2;      // 6291456
    int j = blockIdx.x * blockDim.x + threadIdx.x;
    prep_unit(j, x, D);
    prep_unit(j + half, x, D);
}

// ---------------- kernel 3: fp16 mma GEMM (f16 acc) + bias + GLU + residual --
// CTA: 128 M-rows x (64 a-cols + matching 64 g-cols). B smem rows 0..63 = W row
// n0+r, rows 64..127 = W row 768+n0+r. GLU fused in epilogue. 3 CTAs/SM.
__global__ void __launch_bounds__(256, 3)
gemm_fp16_kernel(const float* __restrict__ bias, const float* __restrict__ x,
                 float* __restrict__ out) {
    extern __shared__ char dsm[];
    uint32_t sb = s2u(dsm);
    const int tid  = threadIdx.x;
    const int lane = tid & 31;
    const int warp = tid >> 5;
    const int wm = warp >> 2;            // 0..1 -> 64 M-rows each
    const int wn = warp & 3;             // 0..3 -> 16 a-cols (+16 g-cols) each
    const int m0 = blockIdx.y * 128;
    const int n0 = blockIdx.x * 64;

    // global->smem loader mapping: each thread owns 2 A units + 2 B units/stage
    const int i0 = tid, i1 = tid + 256;
    const int ar0 = i0 >> 2, au0 = i0 & 3;
    const int ar1 = i1 >> 2, au1 = i1 & 3;
    const __half* asrc0 = g_vh + (size_t)(m0 + ar0) * Hd + au0 * 8;
    const __half* asrc1 = g_vh + (size_t)(m0 + ar1) * Hd + au1 * 8;
    const int wr0 = (ar0 < 64) ? (n0 + ar0) : (704 + n0 + ar0);
    const int wr1 = (ar1 < 64) ? (n0 + ar1) : (704 + n0 + ar1);
    const __half* bsrc0 = g_wh + (size_t)wr0 * Hd + au0 * 8;
    const __half* bsrc1 = g_wh + (size_t)wr1 * Hd + au1 * 8;
    const uint32_t ad0 = (uint32_t)(ar0 * RSB + au0 * 16);
    const uint32_t ad1 = (uint32_t)(ar1 * RSB + au1 * 16);

    // prologue: stages 0..1
#pragma unroll
    for (int s = 0; s < 2; ++s) {
        uint32_t st = sb + s * STG;
        cp16(st + ad0, asrc0 + s * 32);
        cp16(st + ad1, asrc1 + s * 32);
        cp16(st + ATILE + ad0, bsrc0 + s * 32);
        cp16(st + ATILE + ad1, bsrc1 + s * 32);
        asm volatile("cp.async.commit_group;" ::: "memory");
    }

    // ldmatrix per-lane offsets
    const int lro = (lane & 7) + ((lane >> 3) & 1) * 8;
    const int lu  = lane >> 4;
    uint32_t aoff[4], boff[2];
#pragma unroll
    for (int mi = 0; mi < 4; ++mi)
        aoff[mi] = (uint32_t)((wm * 64 + mi * 16 + lro) * RSB + lu * 16);
    boff[0] = (uint32_t)((wn * 16 + lro) * RSB + lu * 16);
    boff[1] = (uint32_t)((64 + wn * 16 + lro) * RSB + lu * 16);

    uint32_t accA[4][2][2], accG[4][2][2];    // f16x2 accumulators
#pragma unroll
    for (int mi = 0; mi < 4; ++mi)
#pragma unroll
        for (int nj = 0; nj < 2; ++nj)
#pragma unroll
            for (int r = 0; r < 2; ++r) { accA[mi][nj][r] = 0u; accG[mi][nj][r] = 0u; }

    for (int t = 0; t < KT; ++t) {
        asm volatile("cp.async.wait_group 1;" ::: "memory");
        __syncthreads();

        if (t + 2 < KT) {
            uint32_t st = sb + ((t + 2) % NSTG) * STG;
            int kw = (t + 2) * 32;
            cp16(st + ad0, asrc0 + kw);
            cp16(st + ad1, asrc1 + kw);
            cp16(st + ATILE + ad0, bsrc0 + kw);
            cp16(st + ATILE + ad1, bsrc1 + kw);
        }
        asm volatile("cp.async.commit_group;" ::: "memory");

        uint32_t ab = sb + (t % NSTG) * STG;
        uint32_t bb = ab + ATILE;
#pragma unroll
        for (int ks = 0; ks < 2; ++ks) {
            uint32_t kadd = (uint32_t)(ks * 32);   // 16 halves = 32B
            uint32_t afr[4][4];
#pragma unroll
            for (int mi = 0; mi < 4; ++mi)
                ldsm4(afr[mi], ab + aoff[mi] + kadd);
            uint32_t ba[4], bg[4];
            ldsm4(ba, bb + boff[0] + kadd);
            ldsm4(bg, bb + boff[1] + kadd);
#pragma unroll
            for (int mi = 0; mi < 4; ++mi) {
                mma16816h(accA[mi][0], afr[mi], ba[0], ba[2]);
                mma16816h(accA[mi][1], afr[mi], ba[1], ba[3]);
                mma16816h(accG[mi][0], afr[mi], bg[0], bg[2]);
                mma16816h(accG[mi][1], afr[mi], bg[1], bg[3]);
            }
        }
    }

    // epilogue: unpack f16 accs, bias + GLU + residual
    const int r  = lane >> 2;
    const int c2 = (lane & 3) * 2;
#pragma unroll
    for (int nj = 0; nj < 2; ++nj) {
        int col = n0 + wn * 16 + nj * 8 + c2;
        float ba0 = __ldg(bias + col),      ba1 = __ldg(bias + col + 1);
        float bg0 = __ldg(bias + Hd + col), bg1 = __ldg(bias + Hd + col + 1);
#pragma unroll
        for (int mi = 0; mi < 4; ++mi) {
            int mrow = m0 + wm * 64 + mi * 16 + r;
            {
                __half2 ah = *reinterpret_cast<__half2*>(&accA[mi][nj][0]);
                __half2 gh = *reinterpret_cast<__half2*>(&accG[mi][nj][0]);
                float a0 = __low2float(ah) + ba0, a1 = __high2float(ah) + ba1;
                float g0 = __low2float(gh) + bg0, g1 = __high2float(gh) + bg1;
                float2 xv = __ldg(reinterpret_cast<const float2*>(x + (size_t)mrow * Hd + col));
                float2 o;
                o.x = a0 * sigmoidf_(g0) + xv.x;
                o.y = a1 * sigmoidf_(g1) + xv.y;
                *reinterpret_cast<float2*>(out + (size_t)mrow * Hd + col) = o;
            }
            {
                int mr2 = mrow + 8;
                __half2 ah = *reinterpret_cast<__half2*>(&accA[mi][nj][1]);
                __half2 gh = *reinterpret_cast<__half2*>(&accG[mi][nj][1]);
                float a0 = __low2float(ah) + ba0, a1 = __high2float(ah) + ba1;
                float g0 = __low2float(gh) + bg0, g1 = __high2float(gh) + bg1;
                float2 xv = __ldg(reinterpret_cast<const float2*>(x + (size_t)mr2 * Hd + col));
                float2 o;
                o.x = a0 * sigmoidf_(g0) + xv.x;
                o.y = a1 * sigmoidf_(g1) + xv.y;
                *reinterpret_cast<float2*>(out + (size_t)mr2 * Hd + col) = o;
            }
        }
    }
}

// ---------------- launch ------------------------------------------------------
extern "C" void kernel_launch(void* const* d_in, const int* in_sizes, int n_in,
                              void* d_out, int out_size) {
    const float* x    = (const float*)d_in[0];   // (8, 8192, 768)
    const float* kern = (const float*)d_in[1];   // (1, 768, 8192)
    const float* D    = (const float*)d_in[2];   // (1, 768)
    const float* W    = (const float*)d_in[3];   // (1536, 768)
    const float* bias = (const float*)d_in[4];   // (1536,)
    float* out = (float*)d_out;                  // (8, 8192, 768)

    cudaFuncSetAttribute(gemm_fp16_kernel,
                         cudaFuncAttributeMaxDynamicSharedMemorySize, GSM);

    // fused: taps (96 blocks) + W conversion (4608 blocks)
    init_kernel<<<96 + (2 * Hd * Hd) / 256, 256>>>(kern, W);

    int half = Mtot * (Hd / 4) / 2;              // 6291456
    prep_v_kernel<<<half / 256, 256>>>(x, D);

    dim3 grid(Hd / 64, Mtot / 128);              // (12, 512)
    gemm_fp16_kernel<<<grid, 256, GSM>>>(bias, x, out);
}

// round 15
// speedup vs baseline: 1.0782x; 1.0557x over previous
#include <cuda_runtime.h>
#include <cuda_fp16.h>
#include <cstdint>

// Problem constants
#define Bb   8
#define Lseq 8192
#define Hd   768
#define Mtot (Bb * Lseq)        // 65536
#define LAMK 0.1f

// GEMM tiling (fp16 mma.sync path, fp16 accumulate)
#define KT    24                // K chunks of 32
#define RSB   80                // smem row stride bytes (40 halves) -> conflict-free ldmatrix
#define ATILE 10240             // 128 rows * 80B
#define STG   20480             // A tile + B tile per stage
#define NSTG  3
#define GSM   (NSTG * STG)      // 61440 bytes dynamic smem -> 3 CTAs/SM

// fused-init grid split
#define TAPS_BLKS  96
#define WCNV_BLKS  ((2 * Hd * Hd) / 256)            // 4608
#define PREP_HALF  (Mtot * (Hd / 4) / 2)            // 6291456 float4 units per half
#define PREP_BLKS  (PREP_HALF / 256)                // 24576

// ---------------- scratch ----------------------------------------------------
__device__ __half g_vh[(size_t)Mtot * Hd];      // silu(x*D + conv) in fp16
__device__ __half g_wh[2 * Hd * Hd];            // W in fp16 (1536 x 768)
__device__ int    g_tap_idx[Hd * Lseq];
__device__ float  g_tap_val[Hd * Lseq];
__device__ int    g_tap_cnt[Hd];

// ---------------- helpers ----------------------------------------------------
__device__ __forceinline__ float sigmoidf_(float z) {
    return 1.0f / (1.0f + __expf(-z));
}

__device__ __forceinline__ uint32_t s2u(const void* p) {
    uint32_t a;
    asm("{ .reg .u64 t; cvta.to.shared.u64 t, %1; cvt.u32.u64 %0, t; }"
        : "=r"(a) : "l"(p));
    return a;
}

__device__ __forceinline__ void cp16(uint32_t dst, const void* src) {
    asm volatile("cp.async.cg.shared.global [%0], [%1], 16;\n"
                 :: "r"(dst), "l"(src));
}

__device__ __forceinline__ void ldsm4(uint32_t* r, uint32_t addr) {
    asm volatile("ldmatrix.sync.aligned.m8n8.x4.shared.b16 {%0,%1,%2,%3}, [%4];"
                 : "=r"(r[0]), "=r"(r[1]), "=r"(r[2]), "=r"(r[3]) : "r"(addr));
}

// fp16-accumulate mma: D,C are 2 regs of f16x2
__device__ __forceinline__ void mma16816h(uint32_t* d, const uint32_t* a,
                                          uint32_t b0, uint32_t b1) {
    asm volatile(
        "mma.sync.aligned.m16n8k16.row.col.f16.f16.f16.f16 "
        "{%0,%1}, {%2,%3,%4,%5}, {%6,%7}, {%0,%1};\n"
        : "+r"(d[0]), "+r"(d[1])
        : "r"(a[0]), "r"(a[1]), "r"(a[2]), "r"(a[3]), "r"(b0), "r"(b1));
}

// ---------------- kernel 1: fused taps + W convert + v = silu(x*D) -----------
// blocks [0,96): soft-threshold + ordered tap compaction (8 warps = 8 h each)
// blocks [96, 96+4608): W fp32 -> fp16
// blocks [96+4608, ...): v = silu(x*D)  (conv term handled by fixup kernel)
__global__ void fused_init_kernel(const float* __restrict__ kern,
                                  const float* __restrict__ W,
                                  const float* __restrict__ x,
                                  const float* __restrict__ D) {
    const int bx = blockIdx.x;
    if (bx < TAPS_BLKS) {
        int h = bx * 8 + (threadIdx.x >> 5);
        int lane = threadIdx.x & 31;
        const float* kr = kern + (size_t)h * Lseq;
        int* ti = g_tap_idx + (size_t)h * Lseq;
        float* tv = g_tap_val + (size_t)h * Lseq;
        int cnt = 0;
        for (int base = 0; base < Lseq; base += 32) {
            float kv = kr[base + lane];
            float mag = fabsf(kv) - LAMK;
            bool p = mag > 0.0f;
            unsigned msk = __ballot_sync(0xffffffffu, p);
            if (p) {
                int pos = cnt + __popc(msk & ((1u << lane) - 1u));
                ti[pos] = base + lane;
                tv[pos] = copysignf(mag, kv);
            }
            cnt += __popc(msk);
        }
        if (lane == 0) g_tap_cnt[h] = cnt;
        return;
    }
    if (bx < TAPS_BLKS + WCNV_BLKS) {
        int i = (bx - TAPS_BLKS) * 256 + threadIdx.x;
        g_wh[i] = __float2half_rn(W[i]);
        return;
    }
    // prep: 2 float4 units per thread (no conv term here)
    const int H4 = Hd / 4;
    int j = (bx - TAPS_BLKS - WCNV_BLKS) * 256 + threadIdx.x;
#pragma unroll
    for (int uu = 0; uu < 2; ++uu) {
        int i = j + uu * PREP_HALF;
        int m = i / H4;
        int h4 = (i - m * H4) * 4;
        float4 xv = *reinterpret_cast<const float4*>(x + (size_t)m * Hd + h4);
        float4 dv = *reinterpret_cast<const float4*>(D + h4);
        float s0 = xv.x * dv.x, s1 = xv.y * dv.y;
        float s2 = xv.z * dv.z, s3 = xv.w * dv.w;
        __half2 h01 = __floats2half2_rn(s0 * sigmoidf_(s0), s1 * sigmoidf_(s1));
        __half2 h23 = __floats2half2_rn(s2 * sigmoidf_(s2), s3 * sigmoidf_(s3));
        uint2 pk;
        pk.x = *reinterpret_cast<uint32_t*>(&h01);
        pk.y = *reinterpret_cast<uint32_t*>(&h23);
        *reinterpret_cast<uint2*>(g_vh + (size_t)m * Hd + h4) = pk;
    }
}

// ---------------- kernel 2: conv fixup (only for h with surviving taps) ------
// One block per h; exits immediately when tap count is zero.
__global__ void conv_fixup_kernel(const float* __restrict__ x,
                                  const float* __restrict__ D) {
    int h = blockIdx.x;
    int cnt = g_tap_cnt[h];
    if (cnt == 0) return;                       // fast path: nothing survived
    const int* ti = g_tap_idx + (size_t)h * Lseq;
    const float* tv = g_tap_val + (size_t)h * Lseq;
    float dh = D[h];
    for (int m = threadIdx.x; m < Mtot; m += blockDim.x) {
        int l = m & (Lseq - 1);
        int b = m >> 13;
        float s = x[(size_t)m * Hd + h] * dh;
        for (int t = 0; t < cnt; ++t) {
            int j = ti[t];
            if (j <= l)
                s += tv[t] * x[((size_t)b * Lseq + (l - j)) * Hd + h];
        }
        g_vh[(size_t)m * Hd + h] = __float2half_rn(s * sigmoidf_(s));
    }
}

// ---------------- kernel 3: fp16 mma GEMM (f16 acc) + bias + GLU + residual --
// CTA: 128 M-rows x (64 a-cols + matching 64 g-cols). B smem rows 0..63 = W row
// n0+r, rows 64..127 = W row 768+n0+r. GLU fused in epilogue. 3 CTAs/SM.
__global__ void __launch_bounds__(256, 3)
gemm_fp16_kernel(const float* __restrict__ bias, const float* __restrict__ x,
                 float* __restrict__ out) {
    extern __shared__ char dsm[];
    uint32_t sb = s2u(dsm);
    const int tid  = threadIdx.x;
    const int lane = tid & 31;
    const int warp = tid >> 5;
    const int wm = warp >> 2;            // 0..1 -> 64 M-rows each
    const int wn = warp & 3;             // 0..3 -> 16 a-cols (+16 g-cols) each
    const int m0 = blockIdx.y * 128;
    const int n0 = blockIdx.x * 64;

    // global->smem loader mapping: each thread owns 2 A units + 2 B units/stage
    const int i0 = tid, i1 = tid + 256;
    const int ar0 = i0 >> 2, au0 = i0 & 3;
    const int ar1 = i1 >> 2, au1 = i1 & 3;
    const __half* asrc0 = g_vh + (size_t)(m0 + ar0) * Hd + au0 * 8;
    const __half* asrc1 = g_vh + (size_t)(m0 + ar1) * Hd + au1 * 8;
    const int wr0 = (ar0 < 64) ? (n0 + ar0) : (704 + n0 + ar0);
    const int wr1 = (ar1 < 64) ? (n0 + ar1) : (704 + n0 + ar1);
    const __half* bsrc0 = g_wh + (size_t)wr0 * Hd + au0 * 8;
    const __half* bsrc1 = g_wh + (size_t)wr1 * Hd + au1 * 8;
    const uint32_t ad0 = (uint32_t)(ar0 * RSB + au0 * 16);
    const uint32_t ad1 = (uint32_t)(ar1 * RSB + au1 * 16);

    // prologue: stages 0..1
#pragma unroll
    for (int s = 0; s < 2; ++s) {
        uint32_t st = sb + s * STG;
        cp16(st + ad0, asrc0 + s * 32);
        cp16(st + ad1, asrc1 + s * 32);
        cp16(st + ATILE + ad0, bsrc0 + s * 32);
        cp16(st + ATILE + ad1, bsrc1 + s * 32);
        asm volatile("cp.async.commit_group;" ::: "memory");
    }

    // ldmatrix per-lane offsets
    const int lro = (lane & 7) + ((lane >> 3) & 1) * 8;
    const int lu  = lane >> 4;
    uint32_t aoff[4], boff[2];
#pragma unroll
    for (int mi = 0; mi < 4; ++mi)
        aoff[mi] = (uint32_t)((wm * 64 + mi * 16 + lro) * RSB + lu * 16);
    boff[0] = (uint32_t)((wn * 16 + lro) * RSB + lu * 16);
    boff[1] = (uint32_t)((64 + wn * 16 + lro) * RSB + lu * 16);

    uint32_t accA[4][2][2], accG[4][2][2];    // f16x2 accumulators
#pragma unroll
    for (int mi = 0; mi < 4; ++mi)
#pragma unroll
        for (int nj = 0; nj < 2; ++nj)
#pragma unroll
            for (int r = 0; r < 2; ++r) { accA[mi][nj][r] = 0u; accG[mi][nj][r] = 0u; }

    for (int t = 0; t < KT; ++t) {
        asm volatile("cp.async.wait_group 1;" ::: "memory");
        __syncthreads();

        if (t + 2 < KT) {
            uint32_t st = sb + ((t + 2) % NSTG) * STG;
            int kw = (t + 2) * 32;
            cp16(st + ad0, asrc0 + kw);
            cp16(st + ad1, asrc1 + kw);
            cp16(st + ATILE + ad0, bsrc0 + kw);
            cp16(st + ATILE + ad1, bsrc1 + kw);
        }
        asm volatile("cp.async.commit_group;" ::: "memory");

        uint32_t ab = sb + (t % NSTG) * STG;
        uint32_t bb = ab + ATILE;
#pragma unroll
        for (int ks = 0; ks < 2; ++ks) {
            uint32_t kadd = (uint32_t)(ks * 32);   // 16 halves = 32B
            uint32_t afr[4][4];
#pragma unroll
            for (int mi = 0; mi < 4; ++mi)
                ldsm4(afr[mi], ab + aoff[mi] + kadd);
            uint32_t ba[4], bg[4];
            ldsm4(ba, bb + boff[0] + kadd);
            ldsm4(bg, bb + boff[1] + kadd);
#pragma unroll
            for (int mi = 0; mi < 4; ++mi) {
                mma16816h(accA[mi][0], afr[mi], ba[0], ba[2]);
                mma16816h(accA[mi][1], afr[mi], ba[1], ba[3]);
                mma16816h(accG[mi][0], afr[mi], bg[0], bg[2]);
                mma16816h(accG[mi][1], afr[mi], bg[1], bg[3]);
            }
        }
    }

    // epilogue: unpack f16 accs, bias + GLU + residual
    const int r  = lane >> 2;
    const int c2 = (lane & 3) * 2;
#pragma unroll
    for (int nj = 0; nj < 2; ++nj) {
        int col = n0 + wn * 16 + nj * 8 + c2;
        float ba0 = __ldg(bias + col),      ba1 = __ldg(bias + col + 1);
        float bg0 = __ldg(bias + Hd + col), bg1 = __ldg(bias + Hd + col + 1);
#pragma unroll
        for (int mi = 0; mi < 4; ++mi) {
            int mrow = m0 + wm * 64 + mi * 16 + r;
            {
                __half2 ah = *reinterpret_cast<__half2*>(&accA[mi][nj][0]);
                __half2 gh = *reinterpret_cast<__half2*>(&accG[mi][nj][0]);
                float a0 = __low2float(ah) + ba0, a1 = __high2float(ah) + ba1;
                float g0 = __low2float(gh) + bg0, g1 = __high2float(gh) + bg1;
                float2 xv = __ldg(reinterpret_cast<const float2*>(x + (size_t)mrow * Hd + col));
                float2 o;
                o.x = a0 * sigmoidf_(g0) + xv.x;
                o.y = a1 * sigmoidf_(g1) + xv.y;
                *reinterpret_cast<float2*>(out + (size_t)mrow * Hd + col) = o;
            }
            {
                int mr2 = mrow + 8;
                __half2 ah = *reinterpret_cast<__half2*>(&accA[mi][nj][1]);
                __half2 gh = *reinterpret_cast<__half2*>(&accG[mi][nj][1]);
                float a0 = __low2float(ah) + ba0, a1 = __high2float(ah) + ba1;
                float g0 = __low2float(gh) + bg0, g1 = __high2float(gh) + bg1;
                float2 xv = __ldg(reinterpret_cast<const float2*>(x + (size_t)mr2 * Hd + col));
                float2 o;
                o.x = a0 * sigmoidf_(g0) + xv.x;
                o.y = a1 * sigmoidf_(g1) + xv.y;
                *reinterpret_cast<float2*>(out + (size_t)mr2 * Hd + col) = o;
            }
        }
    }
}

// ---------------- launch ------------------------------------------------------
extern "C" void kernel_launch(void* const* d_in, const int* in_sizes, int n_in,
                              void* d_out, int out_size) {
    const float* x    = (const float*)d_in[0];   // (8, 8192, 768)
    const float* kern = (const float*)d_in[1];   // (1, 768, 8192)
    const float* D    = (const float*)d_in[2];   // (1, 768)
    const float* W    = (const float*)d_in[3];   // (1536, 768)
    const float* bias = (const float*)d_in[4];   // (1536,)
    float* out = (float*)d_out;                  // (8, 8192, 768)

    cudaFuncSetAttribute(gemm_fp16_kernel,
                         cudaFuncAttributeMaxDynamicSharedMemorySize, GSM);

    // one fused launch: taps + W convert + v = silu(x*D), all independent
    fused_init_kernel<<<TAPS_BLKS + WCNV_BLKS + PREP_BLKS, 256>>>(kern, W, x, D);

    // conv correction for h with surviving taps (no-op when all thresholded)
    conv_fixup_kernel<<<Hd, 256>>>(x, D);

    dim3 grid(Hd / 64, Mtot / 128);              // (12, 512)
    gemm_fp16_kernel<<<grid, 256, GSM>>>(bias, x, out);
}